// round 16
// baseline (speedup 1.0000x reference)
#include <cuda_runtime.h>
#include <cuda_fp16.h>
#include <cstdint>

#define NN      50000
#define NE      1000000
#define ET      1050000     // NE + NN self loops
#define HEADS   8
#define HID     16
#define NCLS    40
#define NEG     0.2f
#define FULL    0xffffffffu

// ---------------- scratch (device globals; no allocation allowed) ----------
__device__ __half g_h[(size_t)NN * 128];    // layer-1 features, fp16 [N,8,16]
__device__ float g_as1[NN * HEADS];
__device__ float g_ad1[NN * HEADS];
__device__ __half g_h2[(size_t)NN * NCLS];  // layer-2 transform, fp16
__device__ float g_as2[NN];
__device__ float g_ad2[NN];
__device__ int   g_deg[NN];
__device__ int   g_cur[NN];
__device__ int   g_off[NN + 1];
__device__ int   g_tmp[49 * 1024];
__device__ int   g_bsum[64];
__device__ int   g_src[ET];                 // src node per CSR slot (grouped by dst)

// ---------------- CSR build ------------------------------------------------
__global__ void k_init() {
    int i = blockIdx.x * blockDim.x + threadIdx.x;
    if (i < NN) { g_deg[i] = 1; g_cur[i] = 0; }   // deg=1 accounts for self loop
}

__global__ void k_hist(const int* __restrict__ ei) {
    int e = blockIdx.x * blockDim.x + threadIdx.x;
    if (e < NE) atomicAdd(&g_deg[ei[NE + e]], 1);
}

__global__ void k_scan1() {
    __shared__ int sh[1024];
    int t = threadIdx.x;
    int idx = blockIdx.x * 1024 + t;
    int v = (idx < NN) ? g_deg[idx] : 0;
    sh[t] = v;
    __syncthreads();
    for (int off = 1; off < 1024; off <<= 1) {
        int tv = (t >= off) ? sh[t - off] : 0;
        __syncthreads();
        sh[t] += tv;
        __syncthreads();
    }
    g_tmp[idx] = sh[t];
    if (t == 1023) g_bsum[blockIdx.x] = sh[t];
}

// fused: scan of the 49 block sums (redundant per block) + apply
__global__ void k_scan23() {
    __shared__ int sh[49];
    int t = threadIdx.x;   // 256
    if (t < 49) sh[t] = g_bsum[t];
    __syncthreads();
    if (t == 0) {
        int s = 0;
        for (int i = 0; i < 49; i++) { s += sh[i]; sh[i] = s; }
    }
    __syncthreads();
    int idx = blockIdx.x * 256 + t;
    if (idx < NN) {
        int b = idx >> 10;
        int pre = (b > 0) ? sh[b - 1] : 0;
        g_off[idx + 1] = g_tmp[idx] + pre;
        if (idx == 0) g_off[0] = 0;
    }
}

// ---------------- scatter edges into CSR slots -----------------------------
__global__ void k_scatter(const int* __restrict__ ei) {
    int e = blockIdx.x * blockDim.x + threadIdx.x;
    if (e >= ET) return;
    int src, dst;
    if (e < NE) { src = ei[e]; dst = ei[NE + e]; }
    else        { src = dst = e - NE; }
    int slot = g_off[dst] + atomicAdd(&g_cur[dst], 1);
    g_src[slot] = src;
}

// ---- GEMM1: h = x @ W1 (50000x128 * 128x128), fused attention dots --------
// 128x128 block tile, 8x8 per-thread microtile via packed fma.rn.f32x2.
#define BM 128
#define BK 32

#define FFMA2(d, a, b) \
    asm("fma.rn.f32x2 %0, %1, %2, %3;" : "=l"(d) : "l"(a), "l"(b), "l"(d))
#define PACK2(d, lo, hi) \
    asm("mov.b64 %0, {%1, %2};" : "=l"(d) : "f"(lo), "f"(hi))
#define UNPACK2(lo, hi, s) \
    asm("mov.b64 {%0, %1}, %2;" : "=f"(lo), "=f"(hi) : "l"(s))

__global__ void __launch_bounds__(256, 2)
k_gemm1(const float* __restrict__ X, const float* __restrict__ W,
        const float* __restrict__ As, const float* __restrict__ Ad) {
    __shared__ float xs[BK][BM];    // transposed X tile
    __shared__ float ws[BK][128];
    int tid = threadIdx.x;          // 256
    int tx = tid & 15;              // col group
    int ty = tid >> 4;              // row group
    int row0 = blockIdx.x * BM;

    unsigned long long acc2[8][4];  // 8 rows x 4 col-pairs, packed f32x2
#pragma unroll
    for (int i = 0; i < 8; i++)
#pragma unroll
        for (int j = 0; j < 4; j++) acc2[i][j] = 0ull;

    int lr  = tid >> 1;             // row this thread loads for X (0..127)
    int lk8 = (tid & 1) * 16;       // k offset group (0 or 16)
    int gr_load = row0 + lr;

    for (int k0 = 0; k0 < 128; k0 += BK) {
        // X tile: 128 rows x 32 k, transposed into xs[k][r]
#pragma unroll
        for (int q = 0; q < 4; q++) {
            float4 v = make_float4(0.f, 0.f, 0.f, 0.f);
            if (gr_load < NN)
                v = *reinterpret_cast<const float4*>(&X[(size_t)gr_load * 128 + k0 + lk8 + q * 4]);
            xs[lk8 + q * 4 + 0][lr] = v.x;
            xs[lk8 + q * 4 + 1][lr] = v.y;
            xs[lk8 + q * 4 + 2][lr] = v.z;
            xs[lk8 + q * 4 + 3][lr] = v.w;
        }
        // W tile: 32 x 128
#pragma unroll
        for (int i = 0; i < 4; i++) {
            int q = i * 256 + tid;
            int kk = q >> 5, c4 = (q & 31) * 4;
            *reinterpret_cast<float4*>(&ws[kk][c4]) =
                *reinterpret_cast<const float4*>(&W[(size_t)(k0 + kk) * 128 + c4]);
        }
        __syncthreads();
#pragma unroll
        for (int kk = 0; kk < BK; kk++) {
            float4 a0 = *reinterpret_cast<const float4*>(&xs[kk][ty * 4]);
            float4 a1 = *reinterpret_cast<const float4*>(&xs[kk][64 + ty * 4]);
            ulonglong2 bq0 = *reinterpret_cast<const ulonglong2*>(&ws[kk][tx * 4]);
            ulonglong2 bq1 = *reinterpret_cast<const ulonglong2*>(&ws[kk][64 + tx * 4]);
            float a[8] = {a0.x, a0.y, a0.z, a0.w, a1.x, a1.y, a1.z, a1.w};
#pragma unroll
            for (int i = 0; i < 8; i++) {
                unsigned long long ap;
                PACK2(ap, a[i], a[i]);
                FFMA2(acc2[i][0], ap, bq0.x);
                FFMA2(acc2[i][1], ap, bq0.y);
                FFMA2(acc2[i][2], ap, bq1.x);
                FFMA2(acc2[i][3], ap, bq1.y);
            }
        }
        __syncthreads();
    }

    // unpack accumulators
    float acc[8][8];
#pragma unroll
    for (int i = 0; i < 8; i++)
#pragma unroll
        for (int j = 0; j < 4; j++)
            UNPACK2(acc[i][j * 2], acc[i][j * 2 + 1], acc2[i][j]);

    // att vectors for this thread's 8 columns (cols tx*4+j and 64+tx*4+j)
    float4 av0 = *reinterpret_cast<const float4*>(&As[tx * 4]);
    float4 av1 = *reinterpret_cast<const float4*>(&As[64 + tx * 4]);
    float4 dv0 = *reinterpret_cast<const float4*>(&Ad[tx * 4]);
    float4 dv1 = *reinterpret_cast<const float4*>(&Ad[64 + tx * 4]);

#pragma unroll
    for (int i = 0; i < 8; i++) {
        int gr = row0 + ((i < 4) ? (ty * 4 + i) : (64 + ty * 4 + i - 4));
        float ps0 = acc[i][0] * av0.x + acc[i][1] * av0.y + acc[i][2] * av0.z + acc[i][3] * av0.w;
        float ps1 = acc[i][4] * av1.x + acc[i][5] * av1.y + acc[i][6] * av1.z + acc[i][7] * av1.w;
        float pd0 = acc[i][0] * dv0.x + acc[i][1] * dv0.y + acc[i][2] * dv0.z + acc[i][3] * dv0.w;
        float pd1 = acc[i][4] * dv1.x + acc[i][5] * dv1.y + acc[i][6] * dv1.z + acc[i][7] * dv1.w;
        ps0 += __shfl_xor_sync(FULL, ps0, 1); ps0 += __shfl_xor_sync(FULL, ps0, 2);
        ps1 += __shfl_xor_sync(FULL, ps1, 1); ps1 += __shfl_xor_sync(FULL, ps1, 2);
        pd0 += __shfl_xor_sync(FULL, pd0, 1); pd0 += __shfl_xor_sync(FULL, pd0, 2);
        pd1 += __shfl_xor_sync(FULL, pd1, 1); pd1 += __shfl_xor_sync(FULL, pd1, 2);
        if (gr < NN) {
            // store h as fp16 (4 halfs = 8B per half-row segment)
            __half2 h01 = __floats2half2_rn(acc[i][0], acc[i][1]);
            __half2 h23 = __floats2half2_rn(acc[i][2], acc[i][3]);
            __half2 h45 = __floats2half2_rn(acc[i][4], acc[i][5]);
            __half2 h67 = __floats2half2_rn(acc[i][6], acc[i][7]);
            *reinterpret_cast<uint2*>(&g_h[(size_t)gr * 128 + tx * 4]) =
                make_uint2(*reinterpret_cast<uint32_t*>(&h01), *reinterpret_cast<uint32_t*>(&h23));
            *reinterpret_cast<uint2*>(&g_h[(size_t)gr * 128 + 64 + tx * 4]) =
                make_uint2(*reinterpret_cast<uint32_t*>(&h45), *reinterpret_cast<uint32_t*>(&h67));
            if ((tx & 3) == 0) {
                int h = tx >> 2;
                g_as1[gr * 8 + h]     = ps0;
                g_ad1[gr * 8 + h]     = pd0;
                g_as1[gr * 8 + 4 + h] = ps1;
                g_ad1[gr * 8 + 4 + h] = pd1;
            }
        }
    }
}

// ---- layer-1 aggregation, warp/node, single-pass softmax, fp16 gather -----
__global__ void k_agg1(const float* __restrict__ b1, const float* __restrict__ W2,
                       const float* __restrict__ as2w, const float* __restrict__ ad2w) {
    int l = threadIdx.x & 31;
    int n = blockIdx.x * 4 + (threadIdx.x >> 5);   // 12500*4 = 50000 exact
    int start = g_off[n], cnt = g_off[n + 1] - start;

    int h = l >> 2;                                 // head per lane
    float adn = g_ad1[n * 8 + h];

    // weighted gather + denominator in ONE pass; lane owns channels 4l..4l+3
    float4 acc = make_float4(0.f, 0.f, 0.f, 0.f);
    float denom = 0.f;
    const __half* hp = g_h + 4 * l;
    int srcn = g_src[start];
    for (int j = 0; j < cnt; j++) {
        int src = srcn;
        if (j + 1 < cnt) srcn = g_src[start + j + 1];
        float e = g_as1[src * 8 + h] + adn;
        e = (e > 0.f) ? e : NEG * e;
        float a = __expf(e);
        denom += a;
        uint2 raw = *reinterpret_cast<const uint2*>(hp + (size_t)src * 128);
        float2 f0 = __half22float2(*reinterpret_cast<__half2*>(&raw.x));
        float2 f1 = __half22float2(*reinterpret_cast<__half2*>(&raw.y));
        acc.x += a * f0.x; acc.y += a * f0.y; acc.z += a * f1.x; acc.w += a * f1.y;
    }
    float inv = 1.f / (denom + 1e-16f);
    acc.x *= inv; acc.y *= inv; acc.z *= inv; acc.w *= inv;

    // --- head mean: sum over the 8 heads (lanes {l&3 + 4h}) ---
#pragma unroll
    for (int off = 4; off <= 16; off <<= 1) {
        acc.x += __shfl_xor_sync(FULL, acc.x, off);
        acc.y += __shfl_xor_sync(FULL, acc.y, off);
        acc.z += __shfl_xor_sync(FULL, acc.z, off);
        acc.w += __shfl_xor_sync(FULL, acc.w, off);
    }
    // every lane holds channels c = 4*(l&3)+k; mean, bias, ELU
    float4 bb = *reinterpret_cast<const float4*>(&b1[4 * (l & 3)]);
    float a0 = acc.x * 0.125f + bb.x;
    float a1 = acc.y * 0.125f + bb.y;
    float a2 = acc.z * 0.125f + bb.z;
    float a3 = acc.w * 0.125f + bb.w;
    a0 = (a0 > 0.f) ? a0 : (__expf(a0) - 1.f);
    a1 = (a1 > 0.f) ? a1 : (__expf(a1) - 1.f);
    a2 = (a2 > 0.f) ? a2 : (__expf(a2) - 1.f);
    a3 = (a3 > 0.f) ? a3 : (__expf(a3) - 1.f);

    // --- broadcast all 16 h1 values, fused layer-2 transform ---
    float h1[16];
#pragma unroll
    for (int k = 0; k < 16; k++) {
        float sv = ((k & 3) == 0) ? a0 : ((k & 3) == 1) ? a1 : ((k & 3) == 2) ? a2 : a3;
        h1[k] = __shfl_sync(FULL, sv, k >> 2);
    }
    float o0 = 0.f, o1 = 0.f;
#pragma unroll
    for (int k = 0; k < 16; k++) o0 += h1[k] * __ldg(&W2[k * NCLS + l]);
    if (l < 8) {
#pragma unroll
        for (int k = 0; k < 16; k++) o1 += h1[k] * __ldg(&W2[k * NCLS + 32 + l]);
    }
    g_h2[(size_t)n * NCLS + l] = __float2half(o0);
    if (l < 8) g_h2[(size_t)n * NCLS + 32 + l] = __float2half(o1);

    float ps = o0 * __ldg(&as2w[l]) + ((l < 8) ? o1 * __ldg(&as2w[32 + l]) : 0.f);
    float pd = o0 * __ldg(&ad2w[l]) + ((l < 8) ? o1 * __ldg(&ad2w[32 + l]) : 0.f);
#pragma unroll
    for (int off = 16; off >= 1; off >>= 1) {
        ps += __shfl_xor_sync(FULL, ps, off);
        pd += __shfl_xor_sync(FULL, pd, off);
    }
    if (l == 0) { g_as2[n] = ps; g_ad2[n] = pd; }
}

// ---- layer-2 aggregation, warp/node, single-pass softmax + log_softmax ----
__global__ void k_agg2(const float* __restrict__ b2, float* __restrict__ out) {
    int l = threadIdx.x & 31;
    int n = blockIdx.x * 4 + (threadIdx.x >> 5);
    int start = g_off[n], cnt = g_off[n + 1] - start;
    float ad = g_ad2[n];

    bool act = (l < 20);                     // lane l covers classes 2l, 2l+1
    float2 acc = make_float2(0.f, 0.f);
    float denom = 0.f;
    const __half* hp = g_h2 + 2 * l;
    int srcn = g_src[start];
    for (int j = 0; j < cnt; j++) {
        int src = srcn;
        if (j + 1 < cnt) srcn = g_src[start + j + 1];
        float e = g_as2[src] + ad;
        e = (e > 0.f) ? e : NEG * e;
        float a = __expf(e);
        denom += a;
        if (act) {
            uint32_t raw = *reinterpret_cast<const uint32_t*>(hp + (size_t)src * NCLS);
            float2 v = __half22float2(*reinterpret_cast<__half2*>(&raw));
            acc.x += a * v.x; acc.y += a * v.y;
        }
    }
    float inv = 1.f / (denom + 1e-16f);

    float rx = 0.f, ry = 0.f;
    if (act) {
        float2 bv = *reinterpret_cast<const float2*>(&b2[2 * l]);
        rx = acc.x * inv + bv.x;
        ry = acc.y * inv + bv.y;
    }
    // log_softmax across the 40 classes
    float mx = act ? fmaxf(rx, ry) : -1e30f;
#pragma unroll
    for (int off = 16; off >= 1; off >>= 1)
        mx = fmaxf(mx, __shfl_xor_sync(FULL, mx, off));
    float se = act ? (__expf(rx - mx) + __expf(ry - mx)) : 0.f;
#pragma unroll
    for (int off = 16; off >= 1; off >>= 1)
        se += __shfl_xor_sync(FULL, se, off);
    float lse = mx + __logf(se);
    if (act) {
        float2 o = make_float2(rx - lse, ry - lse);
        *reinterpret_cast<float2*>(out + (size_t)n * NCLS + 2 * l) = o;
    }
}

// ---------------- launch ---------------------------------------------------
// NOTE: k_gemm1 stays at launch index 3 so the ncu capture lands on it.
extern "C" void kernel_launch(void* const* d_in, const int* in_sizes, int n_in,
                              void* d_out, int out_size) {
    const float* x    = (const float*)d_in[0];
    const int*   ei   = (const int*)  d_in[1];
    const float* W1   = (const float*)d_in[2];
    const float* as1  = (const float*)d_in[3];
    const float* ad1  = (const float*)d_in[4];
    const float* b1   = (const float*)d_in[5];
    const float* W2   = (const float*)d_in[6];
    const float* as2  = (const float*)d_in[7];
    const float* ad2  = (const float*)d_in[8];
    const float* b2   = (const float*)d_in[9];
    float* out = (float*)d_out;

    k_init<<<(NN + 255) / 256, 256>>>();
    k_hist<<<(NE + 255) / 256, 256>>>(ei);
    k_scan1<<<49, 1024>>>();
    k_gemm1<<<(NN + BM - 1) / BM, 256>>>(x, W1, as1, ad1);   // index 3 -> profiled
    k_scan23<<<(NN + 255) / 256, 256>>>();
    k_scatter<<<(ET + 255) / 256, 256>>>(ei);
    k_agg1<<<NN / 4, 128>>>(b1, W2, as2, ad2);
    k_agg2<<<NN / 4, 128>>>(b2, out);
}